// round 12
// baseline (speedup 1.0000x reference)
#include <cuda_runtime.h>
#include <cuda_bf16.h>
#include <cstdint>

#define TOKENS 9216
#define EDIM 256
#define SRCDIM 1024
#define NCODES 16384
#define CAP 128
#define TAU 3e-5f

// ---------------- device scratch ----------------
__device__ float g_z[TOKENS * EDIM];
__device__ __nv_bfloat16 g_zhi[TOKENS * EDIM];
__device__ __nv_bfloat16 g_ehi[NCODES * EDIM];
__device__ __nv_bfloat16 g_xhi[TOKENS * SRCDIM];
__device__ __nv_bfloat16 g_ewhi[EDIM * SRCDIM];   // enc_w^T hi [n][k]
__device__ __nv_bfloat16 g_ewlo[EDIM * SRCDIM];   // enc_w^T lo
__device__ __nv_bfloat16 g_dwt[SRCDIM * EDIM];    // dec_w^T bf16 [n][k]
__device__ float g_e2[NCODES];
__device__ unsigned long long g_minkey[TOKENS];
__device__ int g_cndcnt[TOKENS];
__device__ unsigned int g_cand[TOKENS * CAP];
__device__ float g_losssum;

// ---------------- portable PTX helpers ----------------
__device__ __forceinline__ uint32_t smem_u32(const void* p) {
    uint32_t a;
    asm("{ .reg .u64 t; cvta.to.shared.u64 t, %1; cvt.u32.u64 %0, t; }" : "=r"(a) : "l"(p));
    return a;
}
__device__ __forceinline__ void cp_async16(uint32_t dst, const void* src) {
    asm volatile("cp.async.cg.shared.global [%0], [%1], 16;" :: "r"(dst), "l"(src) : "memory");
}
__device__ __forceinline__ void cp_commit() { asm volatile("cp.async.commit_group;" ::: "memory"); }
__device__ __forceinline__ void cp_wait0() { asm volatile("cp.async.wait_group 0;" ::: "memory"); }
__device__ __forceinline__ void cp_wait1() { asm volatile("cp.async.wait_group 1;" ::: "memory"); }

__device__ __forceinline__ void ldsm_x4(uint32_t& r0, uint32_t& r1, uint32_t& r2, uint32_t& r3,
                                        uint32_t addr) {
    asm volatile("ldmatrix.sync.aligned.m8n8.x4.shared.b16 {%0,%1,%2,%3}, [%4];"
                 : "=r"(r0), "=r"(r1), "=r"(r2), "=r"(r3) : "r"(addr));
}
__device__ __forceinline__ void mma16816(float* c, const uint32_t* a, const uint32_t* b) {
    asm volatile("mma.sync.aligned.m16n8k16.row.col.f32.bf16.bf16.f32 "
                 "{%0,%1,%2,%3}, {%4,%5,%6,%7}, {%8,%9}, {%0,%1,%2,%3};"
                 : "+f"(c[0]), "+f"(c[1]), "+f"(c[2]), "+f"(c[3])
                 : "r"(a[0]), "r"(a[1]), "r"(a[2]), "r"(a[3]), "r"(b[0]), "r"(b[1]));
}

__device__ __forceinline__ unsigned int fkey(float f) {
    unsigned int u = __float_as_uint(f);
    return (u & 0x80000000u) ? ~u : (u | 0x80000000u);
}
__device__ __forceinline__ float inv_fkey(unsigned int k) {
    unsigned int u = (k & 0x80000000u) ? (k & 0x7fffffffu) : ~k;
    return __uint_as_float(u);
}

// ==================== prep_cb (stream 2): init + codebook bf16-hi + e2 ====================
__global__ void __launch_bounds__(256) prep_cb(const float* __restrict__ cb) {
    int bb = blockIdx.x, tid = threadIdx.x;
    int i = bb * 256 + tid;
    if (i < TOKENS) { g_minkey[i] = ~0ull; g_cndcnt[i] = 0; }
    if (i == 0) g_losssum = 0.0f;
    int warp = bb * 8 + (tid >> 5);
    int lane = tid & 31;
    size_t base = (size_t)warp * EDIM;
    float s = 0.0f;
#pragma unroll
    for (int q = 0; q < 8; q++) {
        int k = lane * 8 + q;
        float v = cb[base + k];
        g_ehi[base + k] = __float2bfloat16(v);
        s += v * v;
    }
#pragma unroll
    for (int o = 16; o; o >>= 1) s += __shfl_xor_sync(0xffffffffu, s, o);
    if (lane == 0) g_e2[warp] = s;
}

// ==================== prep_misc: x hi + enc_w^T split + dec_w^T ====================
__global__ void __launch_bounds__(256) prep_misc(const float* __restrict__ x,
                                                 const float* __restrict__ enc_w,
                                                 const float* __restrict__ dec_w) {
    __shared__ float t[32][33];
    int b = blockIdx.x, tid = threadIdx.x;
    int tx = tid & 31, ty = tid >> 5;

    if (b < 256) {
        int n0 = (b & 7) * 32, k0 = (b >> 3) * 32;
#pragma unroll
        for (int r = 0; r < 32; r += 8)
            t[ty + r][tx] = enc_w[(size_t)(k0 + ty + r) * EDIM + n0 + tx];
        __syncthreads();
#pragma unroll
        for (int r = 0; r < 32; r += 8) {
            float v = t[tx][ty + r];
            __nv_bfloat16 h = __float2bfloat16(v);
            size_t o = (size_t)(n0 + ty + r) * SRCDIM + k0 + tx;
            g_ewhi[o] = h;
            g_ewlo[o] = __float2bfloat16(v - __bfloat162float(h));
        }
    } else if (b < 512) {
        int idx = b - 256;
        int n0 = (idx & 31) * 32, k0 = (idx >> 5) * 32;
#pragma unroll
        for (int r = 0; r < 32; r += 8)
            t[ty + r][tx] = dec_w[(size_t)(k0 + ty + r) * SRCDIM + n0 + tx];
        __syncthreads();
#pragma unroll
        for (int r = 0; r < 32; r += 8)
            g_dwt[(size_t)(n0 + ty + r) * EDIM + k0 + tx] = __float2bfloat16(t[tx][ty + r]);
    } else {
        const int total4 = TOKENS * SRCDIM / 4;
        for (int i4 = (b - 512) * 256 + tid; i4 < total4; i4 += 1536 * 256) {
            float4 v = ((const float4*)x)[i4];
            __nv_bfloat162* hi = (__nv_bfloat162*)g_xhi;
            hi[i4 * 2]     = __nv_bfloat162(__float2bfloat16(v.x), __float2bfloat16(v.y));
            hi[i4 * 2 + 1] = __nv_bfloat162(__float2bfloat16(v.z), __float2bfloat16(v.w));
        }
    }
}

// [128 rows][64 k] bf16 tile loader, row 128B, XOR swizzle
__device__ __forceinline__ void load_tile64(uint32_t sdst, const __nv_bfloat16* gsrc,
                                            int rowstride, int tid) {
#pragma unroll
    for (int i = 0; i < 4; i++) {
        int q = tid + 256 * i;
        int r = q >> 3, c = q & 7;
        uint32_t dst = sdst + r * 128 + ((c ^ (r & 7)) << 4);
        cp_async16(dst, gsrc + (size_t)r * rowstride + c * 8);
    }
}

// ==================== encoder: z = x @ enc_w + b, 2-term split (x_hi * (w_hi + w_lo)) ====================
#define EC_SMEM 98304

__global__ void __launch_bounds__(256, 1) enc_mma(const float* __restrict__ bias) {
    extern __shared__ char sm[];
    uint32_t sb = smem_u32(sm);
    int tid = threadIdx.x;
    int lane = tid & 31, wid = tid >> 5;
    int warp_m = wid & 1, warp_n = wid >> 1;
    int m0 = blockIdx.y * 128, n0 = blockIdx.x * 128;

    auto load_stage = [&](int c, int buf) {
        uint32_t base = sb + buf * 49152u;
        load_tile64(base,          g_xhi  + (size_t)m0 * SRCDIM + c * 64, SRCDIM, tid);
        load_tile64(base + 16384u, g_ewhi + (size_t)n0 * SRCDIM + c * 64, SRCDIM, tid);
        load_tile64(base + 32768u, g_ewlo + (size_t)n0 * SRCDIM + c * 64, SRCDIM, tid);
    };

    float acc[4][4][4];
#pragma unroll
    for (int i = 0; i < 4; i++)
#pragma unroll
        for (int j = 0; j < 4; j++)
#pragma unroll
            for (int q = 0; q < 4; q++) acc[i][j][q] = 0.0f;

    load_stage(0, 0);
    cp_commit();

    for (int c = 0; c < 16; c++) {
        if (c < 15) { load_stage(c + 1, (c + 1) & 1); cp_commit(); cp_wait1(); }
        else cp_wait0();
        __syncthreads();

        uint32_t base = sb + (c & 1) * 49152u;
        uint32_t Ah = base, Bh = base + 16384u, Bl = base + 32768u;
#pragma unroll
        for (int kk = 0; kk < 4; kk++) {
            uint32_t bh[2][4], bl[2][4];
#pragma unroll
            for (int jp = 0; jp < 2; jp++) {
                int n = warp_n * 32 + jp * 16 + (lane & 7) + ((lane >> 4) << 3);
                int ch = kk * 2 + ((lane >> 3) & 1);
                uint32_t sw = ((ch ^ (n & 7)) << 4);
                ldsm_x4(bh[jp][0], bh[jp][1], bh[jp][2], bh[jp][3], Bh + n * 128 + sw);
                ldsm_x4(bl[jp][0], bl[jp][1], bl[jp][2], bl[jp][3], Bl + n * 128 + sw);
            }
#pragma unroll
            for (int i = 0; i < 4; i++) {
                int r = warp_m * 64 + i * 16 + (lane & 15);
                int kb = kk * 2 + (lane >> 4);
                uint32_t sw = ((kb ^ (r & 7)) << 4);
                uint32_t ah[4];
                ldsm_x4(ah[0], ah[1], ah[2], ah[3], Ah + r * 128 + sw);
#pragma unroll
                for (int j = 0; j < 4; j++) {
                    mma16816(acc[i][j], ah, &bh[j >> 1][(j & 1) * 2]);
                    mma16816(acc[i][j], ah, &bl[j >> 1][(j & 1) * 2]);
                }
            }
        }
        __syncthreads();
    }

#pragma unroll
    for (int j = 0; j < 4; j++) {
        int n = n0 + warp_n * 32 + j * 8 + (lane & 3) * 2;
        float b0 = bias[n], b1 = bias[n + 1];
#pragma unroll
        for (int i = 0; i < 4; i++) {
            int row = m0 + warp_m * 64 + i * 16 + (lane >> 2);
#pragma unroll
            for (int q = 0; q < 2; q++) {
                int rr = row + q * 8;
                float v0 = acc[i][j][q * 2] + b0;
                float v1 = acc[i][j][q * 2 + 1] + b1;
                *(float2*)(g_z + (size_t)rr * EDIM + n) = make_float2(v0, v1);
                *(__nv_bfloat162*)(g_zhi + (size_t)rr * EDIM + n) =
                    __nv_bfloat162(__float2bfloat16(v0), __float2bfloat16(v1));
            }
        }
    }
}

// ==================== score phase 1 (R8 version): CTA 128x128, warp 64x32, 2 CTAs/SM ====================
// A zhi as 4 k-tiles [128x64] @ [0,64K); B 2 x 16KB @ [64K,96K); e2 @96K; mk @96.5K
#define SCB_OFF  65536
#define SCE2_OFF 98304
#define SCMK_OFF 98816
#define SC_SMEM  99840
#define NCHUNKS  128          // 32 tiles x 4 k-chunks of [128n x 64k]

__global__ void __launch_bounds__(256, 2) score_p1() {
    extern __shared__ char sm[];
    uint32_t sb = smem_u32(sm);
    int tid = threadIdx.x;
    int lane = tid & 31, wid = tid >> 5;
    int warp_m = wid & 1, warp_n = wid >> 1;
    int m0 = blockIdx.y * 128;
    int nbase = blockIdx.x * 4096;

    unsigned long long* mk = (unsigned long long*)(sm + SCMK_OFF);
    float* e2s = (float*)(sm + SCE2_OFF);
    if (tid < 128) mk[tid] = ~0ull;

    // precomputed LDSM offsets (loop-invariant per thread)
    uint32_t aoff[4][4], boff[2][4];
#pragma unroll
    for (int i = 0; i < 4; i++) {
        int r = warp_m * 64 + i * 16 + (lane & 15);
#pragma unroll
        for (int kk = 0; kk < 4; kk++) {
            int ch = kk * 2 + (lane >> 4);
            aoff[i][kk] = (uint32_t)(r * 128 + ((ch ^ (r & 7)) << 4));
        }
    }
#pragma unroll
    for (int jp = 0; jp < 2; jp++) {
        int n = warp_n * 32 + jp * 16 + (lane & 7) + ((lane >> 4) << 3);
#pragma unroll
        for (int kk = 0; kk < 4; kk++) {
            int ch = kk * 2 + ((lane >> 3) & 1);
            boff[jp][kk] = (uint32_t)(n * 128 + ((ch ^ (n & 7)) << 4));
        }
    }

    // persistent A (zhi): 4 k-tiles of [128 rows x 64 k], each row 128B swizzled
    {
        const __nv_bfloat16* zh = g_zhi + (size_t)m0 * 256;
#pragma unroll
        for (int i = 0; i < 16; i++) {
            int q = tid + 256 * i;
            int r = q >> 5, c = q & 31;
            uint32_t dst = sb + (uint32_t)(c >> 3) * 16384u + r * 128 +
                           (((c & 7) ^ (r & 7)) << 4);
            cp_async16(dst, zh + (size_t)r * 256 + c * 8);
        }
        cp_commit();
    }

    auto load_chunk = [&](int c) {
        uint32_t sdst = sb + SCB_OFF + (uint32_t)(c & 1) * 16384u;
        const __nv_bfloat16* gsrc =
            g_ehi + (size_t)(nbase + (c >> 2) * 128) * 256 + (c & 3) * 64;
#pragma unroll
        for (int i = 0; i < 4; i++) {
            int q = tid + 256 * i;
            int r = q >> 3, cc = q & 7;
            uint32_t dst = sdst + r * 128 + ((cc ^ (r & 7)) << 4);
            cp_async16(dst, gsrc + (size_t)r * 256 + cc * 8);
        }
    };

    load_chunk(0); cp_commit();

    float acc[4][4][4];
#pragma unroll
    for (int i = 0; i < 4; i++)
#pragma unroll
        for (int j = 0; j < 4; j++)
#pragma unroll
            for (int q = 0; q < 4; q++) acc[i][j][q] = 0.0f;

    for (int c = 0; c < NCHUNKS; c++) {
        if ((c & 3) == 0 && tid < 128) e2s[tid] = g_e2[nbase + (c >> 2) * 128 + tid];
        if (c + 1 < NCHUNKS) { load_chunk(c + 1); cp_commit(); cp_wait1(); }
        else cp_wait0();
        __syncthreads();

        uint32_t abase = sb + (uint32_t)(c & 3) * 16384u;
        uint32_t bbase = sb + SCB_OFF + (uint32_t)(c & 1) * 16384u;
#pragma unroll
        for (int kk = 0; kk < 4; kk++) {
            uint32_t bf[2][4];
            ldsm_x4(bf[0][0], bf[0][1], bf[0][2], bf[0][3], bbase + boff[0][kk]);
            ldsm_x4(bf[1][0], bf[1][1], bf[1][2], bf[1][3], bbase + boff[1][kk]);
#pragma unroll
            for (int i = 0; i < 4; i++) {
                uint32_t a[4];
                ldsm_x4(a[0], a[1], a[2], a[3], abase + aoff[i][kk]);
#pragma unroll
                for (int j = 0; j < 4; j++)
                    mma16816(acc[i][j], a, &bf[j >> 1][(j & 1) * 2]);
            }
        }

        if ((c & 3) == 3) {
            int n0 = nbase + (c >> 2) * 128;
            // pass 1: running min
#pragma unroll
            for (int i = 0; i < 4; i++) {
#pragma unroll
                for (int half = 0; half < 2; half++) {
                    float best = __int_as_float(0x7f800000);
                    int bn = 0;
#pragma unroll
                    for (int j = 0; j < 4; j++) {
#pragma unroll
                        for (int jj = 0; jj < 2; jj++) {
                            int nl = warp_n * 32 + j * 8 + (lane & 3) * 2 + jj;
                            float s = fmaf(-2.0f, acc[i][j][half * 2 + jj], e2s[nl]);
                            acc[i][j][half * 2 + jj] = s;
                            if (s < best) { best = s; bn = nl; }
                        }
                    }
                    unsigned long long key =
                        ((unsigned long long)fkey(best) << 32) | (unsigned int)(n0 + bn);
                    unsigned long long o = __shfl_xor_sync(0xffffffffu, key, 1);
                    if (o < key) key = o;
                    o = __shfl_xor_sync(0xffffffffu, key, 2);
                    if (o < key) key = o;
                    if ((lane & 3) == 0)
                        atomicMin(&mk[warp_m * 64 + i * 16 + (lane >> 2) + half * 8], key);
                }
            }
            __syncthreads();
            // pass 2: candidate collection
#pragma unroll
            for (int i = 0; i < 4; i++) {
#pragma unroll
                for (int half = 0; half < 2; half++) {
                    int rowl = warp_m * 64 + i * 16 + (lane >> 2) + half * 8;
                    float thresh = inv_fkey((unsigned int)(mk[rowl] >> 32)) + TAU;
                    int rowg = m0 + rowl;
#pragma unroll
                    for (int j = 0; j < 4; j++) {
#pragma unroll
                        for (int jj = 0; jj < 2; jj++) {
                            float s = acc[i][j][half * 2 + jj];
                            acc[i][j][half * 2 + jj] = 0.0f;
                            if (s < thresh) {
                                int n = n0 + warp_n * 32 + j * 8 + (lane & 3) * 2 + jj;
                                int pos = atomicAdd(&g_cndcnt[rowg], 1);
                                if (pos < CAP) g_cand[rowg * CAP + pos] = (unsigned int)n;
                            }
                        }
                    }
                }
            }
        }
        __syncthreads();
    }
    if (tid < 128) atomicMin(&g_minkey[m0 + tid], mk[tid]);
}

// ==================== refine + loss: lane-per-candidate exact fp32 rescore ====================
__global__ void __launch_bounds__(256) refine_loss(const float* __restrict__ cb) {
    __shared__ float zs[8][256];
    __shared__ float ls[8];
    int wid = threadIdx.x >> 5;
    int lane = threadIdx.x & 31;
    int gw = blockIdx.x * 8 + wid;

    // stage this token's z row in smem
    float4* zsh = (float4*)zs[wid];
    const float4* zg = (const float4*)(g_z + (size_t)gw * 256);
    zsh[lane] = zg[lane];
    zsh[lane + 32] = zg[lane + 32];
    __syncwarp();

    int cnt = g_cndcnt[gw];
    if (cnt > CAP) cnt = CAP;
    int idx0 = (int)(g_minkey[gw] & 0xffffffffu);
    unsigned long long best = ~0ull;

    for (int base = 0; base < cnt + 1; base += 32) {
        int c = base + lane;
        unsigned long long key = ~0ull;
        if (c < cnt + 1) {
            int idx = (c == 0) ? idx0 : (int)g_cand[gw * CAP + c - 1];
            const float4* e = (const float4*)(cb + (size_t)idx * 256);
            float a0 = 0.0f, a1 = 0.0f, a2 = 0.0f, a3 = 0.0f;
#pragma unroll 8
            for (int q = 0; q < 64; q++) {
                float4 ev = e[q];
                float4 zv = zsh[q];
                a0 = fmaf(ev.x, zv.x, a0);
                a1 = fmaf(ev.y, zv.y, a1);
                a2 = fmaf(ev.z, zv.z, a2);
                a3 = fmaf(ev.w, zv.w, a3);
            }
            float d = (a0 + a1) + (a2 + a3);
            float s = fmaf(-2.0f, d, g_e2[idx]);
            key = ((unsigned long long)fkey(s) << 32) | (unsigned int)idx;
        }
#pragma unroll
        for (int o = 16; o; o >>= 1) {
            unsigned long long t = __shfl_xor_sync(0xffffffffu, key, o);
            if (t < key) key = t;
        }
        if (key < best) best = key;
    }
    if (lane == 0) g_minkey[gw] = best;
    int bidx = (int)(best & 0xffffffffu);

    // loss: lanes split dims
    const float4* e = (const float4*)(cb + (size_t)bidx * 256);
    float4 e0 = e[lane], e1 = e[lane + 32];
    float4 z0 = zsh[lane], z1 = zsh[lane + 32];
    float dx, l = 0.0f;
    dx = e0.x - z0.x; l += dx * dx;   dx = e0.y - z0.y; l += dx * dx;
    dx = e0.z - z0.z; l += dx * dx;   dx = e0.w - z0.w; l += dx * dx;
    dx = e1.x - z1.x; l += dx * dx;   dx = e1.y - z1.y; l += dx * dx;
    dx = e1.z - z1.z; l += dx * dx;   dx = e1.w - z1.w; l += dx * dx;
#pragma unroll
    for (int o = 16; o; o >>= 1) l += __shfl_xor_sync(0xffffffffu, l, o);
    if (lane == 0) ls[wid] = l;
    __syncthreads();
    if (threadIdx.x == 0) {
        float s = 0.0f;
#pragma unroll
        for (int w = 0; w < 8; w++) s += ls[w];
        atomicAdd(&g_losssum, s);
    }
}

// ==================== decoder: out = ehi[idx] @ dwt^T + dec_b (+ loss writeback) ====================
#define DCB_OFF  65536
#define DCI_OFF  98304
#define DC_SMEM  98816

__device__ __forceinline__ void load_b_stage(uint32_t sdst, const __nv_bfloat16* gsrc, int tid) {
#pragma unroll
    for (int i = 0; i < 4; i++) {
        int q = tid + 256 * i;
        int r = q >> 3, c = q & 7;
        uint32_t dst = sdst + r * 128 + ((c ^ (r & 7)) << 4);
        cp_async16(dst, gsrc + (size_t)r * 256 + c * 8);
    }
}

__global__ void __launch_bounds__(256, 2) dec_kernel(const float* __restrict__ bias,
                                                     float* __restrict__ C, int nout) {
    extern __shared__ char sm[];
    uint32_t sb = smem_u32(sm);
    int tid = threadIdx.x;
    int lane = tid & 31, wid = tid >> 5;
    int warp_m = wid & 1, warp_n = wid >> 1;
    int m0 = blockIdx.y * 128, n0 = blockIdx.x * 128;

    if (blockIdx.x == 0 && blockIdx.y == 0 && tid == 0)
        C[nout - 1] = 1.25f * g_losssum / (float)(TOKENS * EDIM);

    int* idxs = (int*)(sm + DCI_OFF);
    if (tid < 128) idxs[tid] = (int)(g_minkey[m0 + tid] & 0xffffffffu);
    __syncthreads();

#pragma unroll
    for (int i = 0; i < 16; i++) {
        int q = tid + 256 * i;
        int r = q >> 5, c = q & 31;
        uint32_t dst = sb + r * 512 + (c >> 3) * 128 + (((c & 7) ^ (r & 7)) << 4);
        cp_async16(dst, g_ehi + (size_t)idxs[r] * 256 + c * 8);
    }
    cp_commit();
    load_b_stage(sb + DCB_OFF, g_dwt + (size_t)n0 * 256, tid);
    cp_commit();

    float acc[4][4][4];
#pragma unroll
    for (int i = 0; i < 4; i++)
#pragma unroll
        for (int j = 0; j < 4; j++)
#pragma unroll
            for (int q = 0; q < 4; q++) acc[i][j][q] = 0.0f;

    for (int st = 0; st < 4; st++) {
        if (st < 3) {
            load_b_stage(sb + DCB_OFF + ((st + 1) & 1) * 16384,
                         g_dwt + (size_t)n0 * 256 + (st + 1) * 64, tid);
            cp_commit();
            cp_wait1();
        } else cp_wait0();
        __syncthreads();

        uint32_t bbase = sb + DCB_OFF + (st & 1) * 16384;
#pragma unroll
        for (int kk = 0; kk < 4; kk++) {
            uint32_t b[2][4];
#pragma unroll
            for (int jp = 0; jp < 2; jp++) {
                int n = warp_n * 32 + jp * 16 + (lane & 7) + ((lane >> 4) << 3);
                int ch = kk * 2 + ((lane >> 3) & 1);
                ldsm_x4(b[jp][0], b[jp][1], b[jp][2], b[jp][3],
                        bbase + n * 128 + ((ch ^ (n & 7)) << 4));
            }
#pragma unroll
            for (int i = 0; i < 4; i++) {
                int r = warp_m * 64 + i * 16 + (lane & 15);
                int k = st * 64 + kk * 16 + ((lane >> 4) << 3);
                int c32 = k >> 3;
                uint32_t ad = sb + r * 512 + (c32 >> 3) * 128 + (((c32 & 7) ^ (r & 7)) << 4);
                uint32_t a[4];
                ldsm_x4(a[0], a[1], a[2], a[3], ad);
#pragma unroll
                for (int j = 0; j < 4; j++)
                    mma16816(acc[i][j], a, &b[j >> 1][(j & 1) * 2]);
            }
        }
        __syncthreads();
    }

#pragma unroll
    for (int j = 0; j < 4; j++) {
        int n = n0 + warp_n * 32 + j * 8 + (lane & 3) * 2;
        float b0 = bias[n], b1 = bias[n + 1];
#pragma unroll
        for (int i = 0; i < 4; i++) {
            int row = m0 + warp_m * 64 + i * 16 + (lane >> 2);
            *(float2*)(C + (size_t)row * SRCDIM + n) =
                make_float2(acc[i][j][0] + b0, acc[i][j][1] + b1);
            *(float2*)(C + (size_t)(row + 8) * SRCDIM + n) =
                make_float2(acc[i][j][2] + b0, acc[i][j][3] + b1);
        }
    }
}

// ---------------- launch ----------------
extern "C" void kernel_launch(void* const* d_in, const int* in_sizes, int n_in,
                              void* d_out, int out_size) {
    const float* x     = (const float*)d_in[0];
    const float* enc_w = (const float*)d_in[1];
    const float* enc_b = (const float*)d_in[2];
    const float* cb    = (const float*)d_in[3];
    const float* dec_w = (const float*)d_in[4];
    const float* dec_b = (const float*)d_in[5];
    float* out = (float*)d_out;

    static cudaStream_t s2 = nullptr;
    static cudaEvent_t ev0 = nullptr, ev1 = nullptr;
    if (!s2) {
        cudaStreamCreateWithFlags(&s2, cudaStreamNonBlocking);
        cudaEventCreateWithFlags(&ev0, cudaEventDisableTiming);
        cudaEventCreateWithFlags(&ev1, cudaEventDisableTiming);
        cudaFuncSetAttribute(enc_mma, cudaFuncAttributeMaxDynamicSharedMemorySize, EC_SMEM);
        cudaFuncSetAttribute(score_p1, cudaFuncAttributeMaxDynamicSharedMemorySize, SC_SMEM);
        cudaFuncSetAttribute(dec_kernel, cudaFuncAttributeMaxDynamicSharedMemorySize, DC_SMEM);
    }

    cudaEventRecord(ev0, 0);
    cudaStreamWaitEvent(s2, ev0, 0);
    prep_cb<<<2048, 256, 0, s2>>>(cb);
    cudaEventRecord(ev1, s2);

    prep_misc<<<2048, 256>>>(x, enc_w, dec_w);
    enc_mma<<<dim3(EDIM / 128, TOKENS / 128), 256, EC_SMEM>>>(enc_b);

    cudaStreamWaitEvent(0, ev1, 0);
    score_p1<<<dim3(4, TOKENS / 128), 256, SC_SMEM>>>();
    refine_loss<<<TOKENS / 8, 256>>>(cb);
    dec_kernel<<<dim3(SRCDIM / 128, TOKENS / 128), 256, DC_SMEM>>>(dec_b, out, out_size);
}

// round 13
// speedup vs baseline: 1.0786x; 1.0786x over previous
#include <cuda_runtime.h>
#include <cuda_bf16.h>
#include <cstdint>

#define TOKENS 9216
#define EDIM 256
#define SRCDIM 1024
#define NCODES 16384
#define CAP 128
#define TAU 3e-5f

// ---------------- device scratch ----------------
__device__ float g_z[TOKENS * EDIM];
__device__ __nv_bfloat16 g_zhi[TOKENS * EDIM];
__device__ __nv_bfloat16 g_ehi[NCODES * EDIM];
__device__ __nv_bfloat16 g_xhi[TOKENS * SRCDIM];
__device__ __nv_bfloat16 g_ewhi[EDIM * SRCDIM];   // enc_w^T hi [n][k]
__device__ __nv_bfloat16 g_ewlo[EDIM * SRCDIM];   // enc_w^T lo
__device__ __nv_bfloat16 g_dwt[SRCDIM * EDIM];    // dec_w^T bf16 [n][k]
__device__ float g_e2[NCODES];
__device__ unsigned long long g_minkey[TOKENS];
__device__ int g_cndcnt[TOKENS];
__device__ unsigned int g_cand[TOKENS * CAP];
__device__ float g_losssum;

// ---------------- portable PTX helpers ----------------
__device__ __forceinline__ uint32_t smem_u32(const void* p) {
    uint32_t a;
    asm("{ .reg .u64 t; cvta.to.shared.u64 t, %1; cvt.u32.u64 %0, t; }" : "=r"(a) : "l"(p));
    return a;
}
__device__ __forceinline__ void cp_async16(uint32_t dst, const void* src) {
    asm volatile("cp.async.cg.shared.global [%0], [%1], 16;" :: "r"(dst), "l"(src) : "memory");
}
__device__ __forceinline__ void cp_commit() { asm volatile("cp.async.commit_group;" ::: "memory"); }
__device__ __forceinline__ void cp_wait0() { asm volatile("cp.async.wait_group 0;" ::: "memory"); }
__device__ __forceinline__ void cp_wait1() { asm volatile("cp.async.wait_group 1;" ::: "memory"); }

__device__ __forceinline__ void ldsm_x4(uint32_t& r0, uint32_t& r1, uint32_t& r2, uint32_t& r3,
                                        uint32_t addr) {
    asm volatile("ldmatrix.sync.aligned.m8n8.x4.shared.b16 {%0,%1,%2,%3}, [%4];"
                 : "=r"(r0), "=r"(r1), "=r"(r2), "=r"(r3) : "r"(addr));
}
__device__ __forceinline__ void mma16816(float* c, const uint32_t* a, const uint32_t* b) {
    asm volatile("mma.sync.aligned.m16n8k16.row.col.f32.bf16.bf16.f32 "
                 "{%0,%1,%2,%3}, {%4,%5,%6,%7}, {%8,%9}, {%0,%1,%2,%3};"
                 : "+f"(c[0]), "+f"(c[1]), "+f"(c[2]), "+f"(c[3])
                 : "r"(a[0]), "r"(a[1]), "r"(a[2]), "r"(a[3]), "r"(b[0]), "r"(b[1]));
}

__device__ __forceinline__ unsigned int fkey(float f) {
    unsigned int u = __float_as_uint(f);
    return (u & 0x80000000u) ? ~u : (u | 0x80000000u);
}
__device__ __forceinline__ float inv_fkey(unsigned int k) {
    unsigned int u = (k & 0x80000000u) ? (k & 0x7fffffffu) : ~k;
    return __uint_as_float(u);
}

// ==================== prep_cb (stream 2): init + codebook bf16-hi + e2 ====================
__global__ void __launch_bounds__(256) prep_cb(const float* __restrict__ cb) {
    int bb = blockIdx.x, tid = threadIdx.x;
    int i = bb * 256 + tid;
    if (i < TOKENS) { g_minkey[i] = ~0ull; g_cndcnt[i] = 0; }
    if (i == 0) g_losssum = 0.0f;
    int warp = bb * 8 + (tid >> 5);
    int lane = tid & 31;
    size_t base = (size_t)warp * EDIM;
    float s = 0.0f;
#pragma unroll
    for (int q = 0; q < 8; q++) {
        int k = lane * 8 + q;
        float v = cb[base + k];
        g_ehi[base + k] = __float2bfloat16(v);
        s += v * v;
    }
#pragma unroll
    for (int o = 16; o; o >>= 1) s += __shfl_xor_sync(0xffffffffu, s, o);
    if (lane == 0) g_e2[warp] = s;
}

// ==================== prep_misc: x hi + enc_w^T split + dec_w^T ====================
__global__ void __launch_bounds__(256) prep_misc(const float* __restrict__ x,
                                                 const float* __restrict__ enc_w,
                                                 const float* __restrict__ dec_w) {
    __shared__ float t[32][33];
    int b = blockIdx.x, tid = threadIdx.x;
    int tx = tid & 31, ty = tid >> 5;

    if (b < 256) {
        int n0 = (b & 7) * 32, k0 = (b >> 3) * 32;
#pragma unroll
        for (int r = 0; r < 32; r += 8)
            t[ty + r][tx] = enc_w[(size_t)(k0 + ty + r) * EDIM + n0 + tx];
        __syncthreads();
#pragma unroll
        for (int r = 0; r < 32; r += 8) {
            float v = t[tx][ty + r];
            __nv_bfloat16 h = __float2bfloat16(v);
            size_t o = (size_t)(n0 + ty + r) * SRCDIM + k0 + tx;
            g_ewhi[o] = h;
            g_ewlo[o] = __float2bfloat16(v - __bfloat162float(h));
        }
    } else if (b < 512) {
        int idx = b - 256;
        int n0 = (idx & 31) * 32, k0 = (idx >> 5) * 32;
#pragma unroll
        for (int r = 0; r < 32; r += 8)
            t[ty + r][tx] = dec_w[(size_t)(k0 + ty + r) * SRCDIM + n0 + tx];
        __syncthreads();
#pragma unroll
        for (int r = 0; r < 32; r += 8)
            g_dwt[(size_t)(n0 + ty + r) * EDIM + k0 + tx] = __float2bfloat16(t[tx][ty + r]);
    } else {
        const int total4 = TOKENS * SRCDIM / 4;
        for (int i4 = (b - 512) * 256 + tid; i4 < total4; i4 += 1536 * 256) {
            float4 v = ((const float4*)x)[i4];
            __nv_bfloat162* hi = (__nv_bfloat162*)g_xhi;
            hi[i4 * 2]     = __nv_bfloat162(__float2bfloat16(v.x), __float2bfloat16(v.y));
            hi[i4 * 2 + 1] = __nv_bfloat162(__float2bfloat16(v.z), __float2bfloat16(v.w));
        }
    }
}

// [128 rows][64 k] bf16 tile loader, row 128B, XOR swizzle
__device__ __forceinline__ void load_tile64(uint32_t sdst, const __nv_bfloat16* gsrc,
                                            int rowstride, int tid) {
#pragma unroll
    for (int i = 0; i < 4; i++) {
        int q = tid + 256 * i;
        int r = q >> 3, c = q & 7;
        uint32_t dst = sdst + r * 128 + ((c ^ (r & 7)) << 4);
        cp_async16(dst, gsrc + (size_t)r * rowstride + c * 8);
    }
}

// ==================== encoder: z = x @ enc_w + b, 2-term split (x_hi * (w_hi + w_lo)) ====================
#define EC_SMEM 98304

__global__ void __launch_bounds__(256, 1) enc_mma(const float* __restrict__ bias) {
    extern __shared__ char sm[];
    uint32_t sb = smem_u32(sm);
    int tid = threadIdx.x;
    int lane = tid & 31, wid = tid >> 5;
    int warp_m = wid & 1, warp_n = wid >> 1;
    int m0 = blockIdx.y * 128, n0 = blockIdx.x * 128;

    auto load_stage = [&](int c, int buf) {
        uint32_t base = sb + buf * 49152u;
        load_tile64(base,          g_xhi  + (size_t)m0 * SRCDIM + c * 64, SRCDIM, tid);
        load_tile64(base + 16384u, g_ewhi + (size_t)n0 * SRCDIM + c * 64, SRCDIM, tid);
        load_tile64(base + 32768u, g_ewlo + (size_t)n0 * SRCDIM + c * 64, SRCDIM, tid);
    };

    float acc[4][4][4];
#pragma unroll
    for (int i = 0; i < 4; i++)
#pragma unroll
        for (int j = 0; j < 4; j++)
#pragma unroll
            for (int q = 0; q < 4; q++) acc[i][j][q] = 0.0f;

    load_stage(0, 0);
    cp_commit();

    for (int c = 0; c < 16; c++) {
        if (c < 15) { load_stage(c + 1, (c + 1) & 1); cp_commit(); cp_wait1(); }
        else cp_wait0();
        __syncthreads();

        uint32_t base = sb + (c & 1) * 49152u;
        uint32_t Ah = base, Bh = base + 16384u, Bl = base + 32768u;
#pragma unroll
        for (int kk = 0; kk < 4; kk++) {
            uint32_t bh[2][4], bl[2][4];
#pragma unroll
            for (int jp = 0; jp < 2; jp++) {
                int n = warp_n * 32 + jp * 16 + (lane & 7) + ((lane >> 4) << 3);
                int ch = kk * 2 + ((lane >> 3) & 1);
                uint32_t sw = ((ch ^ (n & 7)) << 4);
                ldsm_x4(bh[jp][0], bh[jp][1], bh[jp][2], bh[jp][3], Bh + n * 128 + sw);
                ldsm_x4(bl[jp][0], bl[jp][1], bl[jp][2], bl[jp][3], Bl + n * 128 + sw);
            }
#pragma unroll
            for (int i = 0; i < 4; i++) {
                int r = warp_m * 64 + i * 16 + (lane & 15);
                int kb = kk * 2 + (lane >> 4);
                uint32_t sw = ((kb ^ (r & 7)) << 4);
                uint32_t ah[4];
                ldsm_x4(ah[0], ah[1], ah[2], ah[3], Ah + r * 128 + sw);
#pragma unroll
                for (int j = 0; j < 4; j++) {
                    mma16816(acc[i][j], ah, &bh[j >> 1][(j & 1) * 2]);
                    mma16816(acc[i][j], ah, &bl[j >> 1][(j & 1) * 2]);
                }
            }
        }
        __syncthreads();
    }

#pragma unroll
    for (int j = 0; j < 4; j++) {
        int n = n0 + warp_n * 32 + j * 8 + (lane & 3) * 2;
        float b0 = bias[n], b1 = bias[n + 1];
#pragma unroll
        for (int i = 0; i < 4; i++) {
            int row = m0 + warp_m * 64 + i * 16 + (lane >> 2);
#pragma unroll
            for (int q = 0; q < 2; q++) {
                int rr = row + q * 8;
                float v0 = acc[i][j][q * 2] + b0;
                float v1 = acc[i][j][q * 2 + 1] + b1;
                *(float2*)(g_z + (size_t)rr * EDIM + n) = make_float2(v0, v1);
                *(__nv_bfloat162*)(g_zhi + (size_t)rr * EDIM + n) =
                    __nv_bfloat162(__float2bfloat16(v0), __float2bfloat16(v1));
            }
        }
    }
}

// ==================== score phase 1 (R8 version): CTA 128x128, warp 64x32, 2 CTAs/SM ====================
#define SCB_OFF  65536
#define SCE2_OFF 98304
#define SCMK_OFF 98816
#define SC_SMEM  99840
#define NCHUNKS  128          // 32 tiles x 4 k-chunks of [128n x 64k]

__global__ void __launch_bounds__(256, 2) score_p1() {
    extern __shared__ char sm[];
    uint32_t sb = smem_u32(sm);
    int tid = threadIdx.x;
    int lane = tid & 31, wid = tid >> 5;
    int warp_m = wid & 1, warp_n = wid >> 1;
    int m0 = blockIdx.y * 128;
    int nbase = blockIdx.x * 4096;

    unsigned long long* mk = (unsigned long long*)(sm + SCMK_OFF);
    float* e2s = (float*)(sm + SCE2_OFF);
    if (tid < 128) mk[tid] = ~0ull;

    uint32_t aoff[4][4], boff[2][4];
#pragma unroll
    for (int i = 0; i < 4; i++) {
        int r = warp_m * 64 + i * 16 + (lane & 15);
#pragma unroll
        for (int kk = 0; kk < 4; kk++) {
            int ch = kk * 2 + (lane >> 4);
            aoff[i][kk] = (uint32_t)(r * 128 + ((ch ^ (r & 7)) << 4));
        }
    }
#pragma unroll
    for (int jp = 0; jp < 2; jp++) {
        int n = warp_n * 32 + jp * 16 + (lane & 7) + ((lane >> 4) << 3);
#pragma unroll
        for (int kk = 0; kk < 4; kk++) {
            int ch = kk * 2 + ((lane >> 3) & 1);
            boff[jp][kk] = (uint32_t)(n * 128 + ((ch ^ (n & 7)) << 4));
        }
    }

    {
        const __nv_bfloat16* zh = g_zhi + (size_t)m0 * 256;
#pragma unroll
        for (int i = 0; i < 16; i++) {
            int q = tid + 256 * i;
            int r = q >> 5, c = q & 31;
            uint32_t dst = sb + (uint32_t)(c >> 3) * 16384u + r * 128 +
                           (((c & 7) ^ (r & 7)) << 4);
            cp_async16(dst, zh + (size_t)r * 256 + c * 8);
        }
        cp_commit();
    }

    auto load_chunk = [&](int c) {
        uint32_t sdst = sb + SCB_OFF + (uint32_t)(c & 1) * 16384u;
        const __nv_bfloat16* gsrc =
            g_ehi + (size_t)(nbase + (c >> 2) * 128) * 256 + (c & 3) * 64;
#pragma unroll
        for (int i = 0; i < 4; i++) {
            int q = tid + 256 * i;
            int r = q >> 3, cc = q & 7;
            uint32_t dst = sdst + r * 128 + ((cc ^ (r & 7)) << 4);
            cp_async16(dst, gsrc + (size_t)r * 256 + cc * 8);
        }
    };

    load_chunk(0); cp_commit();

    float acc[4][4][4];
#pragma unroll
    for (int i = 0; i < 4; i++)
#pragma unroll
        for (int j = 0; j < 4; j++)
#pragma unroll
            for (int q = 0; q < 4; q++) acc[i][j][q] = 0.0f;

    for (int c = 0; c < NCHUNKS; c++) {
        if ((c & 3) == 0 && tid < 128) e2s[tid] = g_e2[nbase + (c >> 2) * 128 + tid];
        if (c + 1 < NCHUNKS) { load_chunk(c + 1); cp_commit(); cp_wait1(); }
        else cp_wait0();
        __syncthreads();

        uint32_t abase = sb + (uint32_t)(c & 3) * 16384u;
        uint32_t bbase = sb + SCB_OFF + (uint32_t)(c & 1) * 16384u;
#pragma unroll
        for (int kk = 0; kk < 4; kk++) {
            uint32_t bf[2][4];
            ldsm_x4(bf[0][0], bf[0][1], bf[0][2], bf[0][3], bbase + boff[0][kk]);
            ldsm_x4(bf[1][0], bf[1][1], bf[1][2], bf[1][3], bbase + boff[1][kk]);
#pragma unroll
            for (int i = 0; i < 4; i++) {
                uint32_t a[4];
                ldsm_x4(a[0], a[1], a[2], a[3], abase + aoff[i][kk]);
#pragma unroll
                for (int j = 0; j < 4; j++)
                    mma16816(acc[i][j], a, &bf[j >> 1][(j & 1) * 2]);
            }
        }

        if ((c & 3) == 3) {
            int n0 = nbase + (c >> 2) * 128;
#pragma unroll
            for (int i = 0; i < 4; i++) {
#pragma unroll
                for (int half = 0; half < 2; half++) {
                    float best = __int_as_float(0x7f800000);
                    int bn = 0;
#pragma unroll
                    for (int j = 0; j < 4; j++) {
#pragma unroll
                        for (int jj = 0; jj < 2; jj++) {
                            int nl = warp_n * 32 + j * 8 + (lane & 3) * 2 + jj;
                            float s = fmaf(-2.0f, acc[i][j][half * 2 + jj], e2s[nl]);
                            acc[i][j][half * 2 + jj] = s;
                            if (s < best) { best = s; bn = nl; }
                        }
                    }
                    unsigned long long key =
                        ((unsigned long long)fkey(best) << 32) | (unsigned int)(n0 + bn);
                    unsigned long long o = __shfl_xor_sync(0xffffffffu, key, 1);
                    if (o < key) key = o;
                    o = __shfl_xor_sync(0xffffffffu, key, 2);
                    if (o < key) key = o;
                    if ((lane & 3) == 0)
                        atomicMin(&mk[warp_m * 64 + i * 16 + (lane >> 2) + half * 8], key);
                }
            }
            __syncthreads();
#pragma unroll
            for (int i = 0; i < 4; i++) {
#pragma unroll
                for (int half = 0; half < 2; half++) {
                    int rowl = warp_m * 64 + i * 16 + (lane >> 2) + half * 8;
                    float thresh = inv_fkey((unsigned int)(mk[rowl] >> 32)) + TAU;
                    int rowg = m0 + rowl;
#pragma unroll
                    for (int j = 0; j < 4; j++) {
#pragma unroll
                        for (int jj = 0; jj < 2; jj++) {
                            float s = acc[i][j][half * 2 + jj];
                            acc[i][j][half * 2 + jj] = 0.0f;
                            if (s < thresh) {
                                int n = n0 + warp_n * 32 + j * 8 + (lane & 3) * 2 + jj;
                                int pos = atomicAdd(&g_cndcnt[rowg], 1);
                                if (pos < CAP) g_cand[rowg * CAP + pos] = (unsigned int)n;
                            }
                        }
                    }
                }
            }
        }
        __syncthreads();
    }
    if (tid < 128) atomicMin(&g_minkey[m0 + tid], mk[tid]);
}

// ==================== refine + loss (R8 form): warp-per-token, coalesced ====================
__global__ void __launch_bounds__(256) refine_loss(const float* __restrict__ cb) {
    __shared__ float ls[8];
    int wid = threadIdx.x >> 5;
    int gw = blockIdx.x * 8 + wid;
    int lane = threadIdx.x & 31;
    const float4* z = (const float4*)(g_z + (size_t)gw * 256);
    float4 z0 = z[lane * 2], z1 = z[lane * 2 + 1];
    int cnt = g_cndcnt[gw];
    if (cnt > CAP) cnt = CAP;
    unsigned long long best = ~0ull;
    int idx0 = (int)(g_minkey[gw] & 0xffffffffu);
    for (int c = -1; c < cnt; c++) {
        int idx = (c < 0) ? idx0 : (int)g_cand[gw * CAP + c];
        const float4* e = (const float4*)(cb + (size_t)idx * 256);
        float4 e0 = e[lane * 2], e1 = e[lane * 2 + 1];
        float d = z0.x * e0.x + z0.y * e0.y + z0.z * e0.z + z0.w * e0.w
                + z1.x * e1.x + z1.y * e1.y + z1.z * e1.z + z1.w * e1.w;
#pragma unroll
        for (int o = 16; o; o >>= 1) d += __shfl_xor_sync(0xffffffffu, d, o);
        float s = fmaf(-2.0f, d, g_e2[idx]);
        unsigned long long key = ((unsigned long long)fkey(s) << 32) | (unsigned int)idx;
        if (key < best) best = key;
    }
    int bidx = (int)(best & 0xffffffffu);
    if (lane == 0) g_minkey[gw] = best;
    const float4* e = (const float4*)(cb + (size_t)bidx * 256);
    float4 e0 = e[lane * 2], e1 = e[lane * 2 + 1];
    float dx, l = 0.0f;
    dx = e0.x - z0.x; l += dx * dx;   dx = e0.y - z0.y; l += dx * dx;
    dx = e0.z - z0.z; l += dx * dx;   dx = e0.w - z0.w; l += dx * dx;
    dx = e1.x - z1.x; l += dx * dx;   dx = e1.y - z1.y; l += dx * dx;
    dx = e1.z - z1.z; l += dx * dx;   dx = e1.w - z1.w; l += dx * dx;
#pragma unroll
    for (int o = 16; o; o >>= 1) l += __shfl_xor_sync(0xffffffffu, l, o);
    if (lane == 0) ls[wid] = l;
    __syncthreads();
    if (threadIdx.x == 0) {
        float s = 0.0f;
#pragma unroll
        for (int w = 0; w < 8; w++) s += ls[w];
        atomicAdd(&g_losssum, s);
    }
}

// ==================== decoder: out = ehi[idx] @ dwt^T + dec_b (+ loss writeback) ====================
#define DCB_OFF  65536
#define DCI_OFF  98304
#define DC_SMEM  98816

__device__ __forceinline__ void load_b_stage(uint32_t sdst, const __nv_bfloat16* gsrc, int tid) {
#pragma unroll
    for (int i = 0; i < 4; i++) {
        int q = tid + 256 * i;
        int r = q >> 3, c = q & 7;
        uint32_t dst = sdst + r * 128 + ((c ^ (r & 7)) << 4);
        cp_async16(dst, gsrc + (size_t)r * 256 + c * 8);
    }
}

__global__ void __launch_bounds__(256, 2) dec_kernel(const float* __restrict__ bias,
                                                     float* __restrict__ C, int nout) {
    extern __shared__ char sm[];
    uint32_t sb = smem_u32(sm);
    int tid = threadIdx.x;
    int lane = tid & 31, wid = tid >> 5;
    int warp_m = wid & 1, warp_n = wid >> 1;
    int m0 = blockIdx.y * 128, n0 = blockIdx.x * 128;

    if (blockIdx.x == 0 && blockIdx.y == 0 && tid == 0)
        C[nout - 1] = 1.25f * g_losssum / (float)(TOKENS * EDIM);

    int* idxs = (int*)(sm + DCI_OFF);
    if (tid < 128) idxs[tid] = (int)(g_minkey[m0 + tid] & 0xffffffffu);
    __syncthreads();

#pragma unroll
    for (int i = 0; i < 16; i++) {
        int q = tid + 256 * i;
        int r = q >> 5, c = q & 31;
        uint32_t dst = sb + r * 512 + (c >> 3) * 128 + (((c & 7) ^ (r & 7)) << 4);
        cp_async16(dst, g_ehi + (size_t)idxs[r] * 256 + c * 8);
    }
    cp_commit();
    load_b_stage(sb + DCB_OFF, g_dwt + (size_t)n0 * 256, tid);
    cp_commit();

    float acc[4][4][4];
#pragma unroll
    for (int i = 0; i < 4; i++)
#pragma unroll
        for (int j = 0; j < 4; j++)
#pragma unroll
            for (int q = 0; q < 4; q++) acc[i][j][q] = 0.0f;

    for (int st = 0; st < 4; st++) {
        if (st < 3) {
            load_b_stage(sb + DCB_OFF + ((st + 1) & 1) * 16384,
                         g_dwt + (size_t)n0 * 256 + (st + 1) * 64, tid);
            cp_commit();
            cp_wait1();
        } else cp_wait0();
        __syncthreads();

        uint32_t bbase = sb + DCB_OFF + (st & 1) * 16384;
#pragma unroll
        for (int kk = 0; kk < 4; kk++) {
            uint32_t b[2][4];
#pragma unroll
            for (int jp = 0; jp < 2; jp++) {
                int n = warp_n * 32 + jp * 16 + (lane & 7) + ((lane >> 4) << 3);
                int ch = kk * 2 + ((lane >> 3) & 1);
                ldsm_x4(b[jp][0], b[jp][1], b[jp][2], b[jp][3],
                        bbase + n * 128 + ((ch ^ (n & 7)) << 4));
            }
#pragma unroll
            for (int i = 0; i < 4; i++) {
                int r = warp_m * 64 + i * 16 + (lane & 15);
                int k = st * 64 + kk * 16 + ((lane >> 4) << 3);
                int c32 = k >> 3;
                uint32_t ad = sb + r * 512 + (c32 >> 3) * 128 + (((c32 & 7) ^ (r & 7)) << 4);
                uint32_t a[4];
                ldsm_x4(a[0], a[1], a[2], a[3], ad);
#pragma unroll
                for (int j = 0; j < 4; j++)
                    mma16816(acc[i][j], a, &b[j >> 1][(j & 1) * 2]);
            }
        }
        __syncthreads();
    }

#pragma unroll
    for (int j = 0; j < 4; j++) {
        int n = n0 + warp_n * 32 + j * 8 + (lane & 3) * 2;
        float b0 = bias[n], b1 = bias[n + 1];
#pragma unroll
        for (int i = 0; i < 4; i++) {
            int row = m0 + warp_m * 64 + i * 16 + (lane >> 2);
            *(float2*)(C + (size_t)row * SRCDIM + n) =
                make_float2(acc[i][j][0] + b0, acc[i][j][1] + b1);
            *(float2*)(C + (size_t)(row + 8) * SRCDIM + n) =
                make_float2(acc[i][j][2] + b0, acc[i][j][3] + b1);
        }
    }
}

// ---------------- launch ----------------
extern "C" void kernel_launch(void* const* d_in, const int* in_sizes, int n_in,
                              void* d_out, int out_size) {
    const float* x     = (const float*)d_in[0];
    const float* enc_w = (const float*)d_in[1];
    const float* enc_b = (const float*)d_in[2];
    const float* cb    = (const float*)d_in[3];
    const float* dec_w = (const float*)d_in[4];
    const float* dec_b = (const float*)d_in[5];
    float* out = (float*)d_out;

    static cudaStream_t s2 = nullptr;
    static cudaEvent_t ev0 = nullptr, ev1 = nullptr;
    if (!s2) {
        cudaStreamCreateWithFlags(&s2, cudaStreamNonBlocking);
        cudaEventCreateWithFlags(&ev0, cudaEventDisableTiming);
        cudaEventCreateWithFlags(&ev1, cudaEventDisableTiming);
        cudaFuncSetAttribute(enc_mma, cudaFuncAttributeMaxDynamicSharedMemorySize, EC_SMEM);
        cudaFuncSetAttribute(score_p1, cudaFuncAttributeMaxDynamicSharedMemorySize, SC_SMEM);
        cudaFuncSetAttribute(dec_kernel, cudaFuncAttributeMaxDynamicSharedMemorySize, DC_SMEM);
    }

    cudaEventRecord(ev0, 0);
    cudaStreamWaitEvent(s2, ev0, 0);
    prep_cb<<<2048, 256, 0, s2>>>(cb);
    cudaEventRecord(ev1, s2);

    prep_misc<<<2048, 256>>>(x, enc_w, dec_w);
    enc_mma<<<dim3(EDIM / 128, TOKENS / 128), 256, EC_SMEM>>>(enc_b);

    cudaStreamWaitEvent(0, ev1, 0);
    score_p1<<<dim3(4, TOKENS / 128), 256, SC_SMEM>>>();
    refine_loss<<<TOKENS / 8, 256>>>(cb);
    dec_kernel<<<dim3(SRCDIM / 128, TOKENS / 128), 256, DC_SMEM>>>(dec_b, out, out_size);
}